// round 13
// baseline (speedup 1.0000x reference)
#include <cuda_runtime.h>
#include <cuda_fp16.h>
#include <math.h>
#include <stdint.h>

#define NN 8192
#define DD 128
#define NC 256
#define MT 128
#define NT (NN / MT)                      // 64
#define NPAIRS (NT * (NT + 1) / 2)        // 2080
#define KHALF 64
#define MARG 8
#define PARTB 16384                        // 128 rows x 64 halves (128B/row)

typedef unsigned long long u64t;

// ---------------- device globals ----------------
__device__ __half g_hH[NN * DD];
__device__ __half g_hR[NN * DD];
__device__ float g_sq[NN];
__device__ int   g_lab[NN];
__device__ int   g_cnt[NC];
__device__ int   g_is64;
__device__ u64t  g_posP[NN];   // (bits(dist)<<32)|(NN-1-j), atomicMax
__device__ u64t  g_negP[NN];   // (bits(dist)<<32)|j,        atomicMin

#define F_INF __int_as_float(0x7f800000)

// smem: parts 0..3 = Ah Ar Bh Br (16KB each), then control
#define OFF_SQROW  65536
#define OFF_SQCOL  66048
#define OFF_LABROW 66560
#define OFF_LABCOL 67072
#define OFF_ROWP   67584
#define OFF_ROWN   68608
#define OFF_COLP   69632
#define OFF_COLN   70656
#define SMEM_TOTAL 71680

// ---------------- aux kernels ----------------
__global__ void detect_kernel(const int* __restrict__ labw) {
    if (threadIdx.x == 0) {
        int any = 0;
        for (int i = 0; i < 256; i++) any |= labw[2 * i + 1];
        g_is64 = (any == 0) ? 1 : 0;
    }
}

__global__ void convert_labels_kernel(const void* __restrict__ labels) {
    int i = blockIdx.x * blockDim.x + threadIdx.x;
    if (i >= NN) return;
    int v;
    if (g_is64) v = (int)((const long long*)labels)[i];
    else        v = ((const int*)labels)[i];
    g_lab[i] = v;
    g_posP[i] = 0ull;
    g_negP[i] = ~0ull;
    if (i < NC) g_cnt[i] = 0;
}

__global__ void hist_kernel() {
    int i = blockIdx.x * blockDim.x + threadIdx.x;
    if (i < NN) atomicAdd(&g_cnt[g_lab[i] & (NC - 1)], 1);
}

// normalize, sq, fp16 2-way split (h = fp16(x), r = fp16(x - h))
__global__ void normalize_split_kernel(const float* __restrict__ x) {
    int row = blockIdx.x;
    int t = threadIdx.x;
    float v = x[row * DD + t];
    float s = v * v;
    #pragma unroll
    for (int o = 16; o > 0; o >>= 1) s += __shfl_xor_sync(0xffffffffu, s, o);
    __shared__ float ws[4];
    __shared__ float ws2[4];
    int warp = t >> 5, lane = t & 31;
    if (lane == 0) ws[warp] = s;
    __syncthreads();
    float tot = ws[0] + ws[1] + ws[2] + ws[3];
    float nrm = __fsqrt_rn(tot);
    float xn  = __fdiv_rn(v, nrm);
    float s2 = xn * xn;
    #pragma unroll
    for (int o = 16; o > 0; o >>= 1) s2 += __shfl_xor_sync(0xffffffffu, s2, o);
    if (lane == 0) ws2[warp] = s2;
    __syncthreads();
    if (t == 0) g_sq[row] = ws2[0] + ws2[1] + ws2[2] + ws2[3];

    __half h = __float2half_rn(xn);
    float r1 = xn - __half2float(h);
    g_hH[row * DD + t] = h;
    g_hR[row * DD + t] = __float2half_rn(r1);
}

// ---------------- guarded exact-order compares (dist semantics on d2) ----------------
__device__ __forceinline__ bool gtPos(int bN, int iN, int bC, int iC) {
    if (bN == bC) return iN < iC;
    if (bN > bC + MARG) return true;
    if (bN + MARG < bC) return false;
    float dn = __fsqrt_rn(__int_as_float(bN));
    float dc = __fsqrt_rn(__int_as_float(bC));
    if (dn != dc) return dn > dc;
    return iN < iC;
}
__device__ __forceinline__ bool ltNeg(int bN, int iN, int bC, int iC) {
    if (bN == bC) return iN < iC;
    if (bN + MARG < bC) return true;
    if (bN > bC + MARG) return false;
    float dn = __fsqrt_rn(__int_as_float(bN));
    float dc = __fsqrt_rn(__int_as_float(bC));
    if (dn != dc) return dn < dc;
    return iN < iC;
}

// ---------------- HMMA miner ----------------
extern __shared__ __align__(128) char dynsmem[];

__global__ void __launch_bounds__(256, 1) mine_kernel() {
    // triangular pair decode
    int t = blockIdx.x, I = 0;
    while (t >= NT - I) { t -= NT - I; I++; }
    const int J = I + t;
    const int rowBase = I * MT, colBase = J * MT;
    const bool offdiag = (I != J);

    char* smem = dynsmem;
    float* sSqRow = (float*)(smem + OFF_SQROW);
    float* sSqCol = (float*)(smem + OFF_SQCOL);
    int*   sLabRow = (int*)(smem + OFF_LABROW);
    int*   sLabCol = (int*)(smem + OFF_LABCOL);
    u64t*  sRowP = (u64t*)(smem + OFF_ROWP);
    u64t*  sRowN = (u64t*)(smem + OFF_ROWN);
    u64t*  sColP = (u64t*)(smem + OFF_COLP);
    u64t*  sColN = (u64t*)(smem + OFF_COLN);

    const int tid = threadIdx.x, wid = tid >> 5, lane = tid & 31;
    const int g = lane >> 2, tig = lane & 3;
    const int warpRow = wid >> 2, warpCol = wid & 3;   // 2x4 warp grid, 64x32 tiles

    if (tid < MT) {
        sSqRow[tid]  = g_sq[rowBase + tid];
        sLabRow[tid] = g_lab[rowBase + tid];
        sRowP[tid] = 0ull;  sRowN[tid] = ~0ull;
    } else {
        int u = tid - MT;
        sSqCol[u]  = g_sq[colBase + u];
        sLabCol[u] = g_lab[colBase + u];
        sColP[u] = 0ull;  sColN[u] = ~0ull;
    }

    float acc[4][4][4];
    #pragma unroll
    for (int a = 0; a < 4; a++)
        #pragma unroll
        for (int b = 0; b < 4; b++)
            #pragma unroll
            for (int c = 0; c < 4; c++) acc[a][b][c] = 0.0f;

    const __half* srcs[4] = {g_hH + (size_t)rowBase * DD, g_hR + (size_t)rowBase * DD,
                             g_hH + (size_t)colBase * DD, g_hR + (size_t)colBase * DD};

    for (int stage = 0; stage < 2; ++stage) {
        __syncthreads();   // previous stage's mma done with smem
        // fill 4 parts: 16B chunks, XOR-swizzled rows (conflict-free LDS/STS)
        for (int c = tid; c < 4096; c += 256) {
            int part = c >> 10, rem = c & 1023, row = rem >> 3, ch = rem & 7;
            const __half* src = srcs[part] + (size_t)row * DD + stage * KHALF + ch * 8;
            uint4 v = *(const uint4*)src;
            uint32_t off = part * PARTB + row * 128 + ((ch * 16) ^ ((row & 7) << 4));
            *(uint4*)(smem + off) = v;
        }
        __syncthreads();

        const int paP[3] = {0, 0, 1}, pbP[3] = {2, 3, 2};   // hh, hr, rh
        #pragma unroll
        for (int prod = 0; prod < 3; ++prod) {
            const uint32_t aBase = paP[prod] * PARTB;
            const uint32_t bBase = pbP[prod] * PARTB;
            #pragma unroll
            for (int ks = 0; ks < 4; ++ks) {
                const uint32_t bo0 = ks * 32 + tig * 4, bo1 = bo0 + 16;
                uint32_t af[4][4], bf[4][2];
                #pragma unroll
                for (int mr = 0; mr < 4; mr++) {
                    int r0 = warpRow * 64 + mr * 16 + g, r1 = r0 + 8;
                    uint32_t sw0 = (r0 & 7) << 4;
                    af[mr][0] = *(const uint32_t*)(smem + aBase + r0 * 128 + (bo0 ^ sw0));
                    af[mr][1] = *(const uint32_t*)(smem + aBase + r1 * 128 + (bo0 ^ sw0));
                    af[mr][2] = *(const uint32_t*)(smem + aBase + r0 * 128 + (bo1 ^ sw0));
                    af[mr][3] = *(const uint32_t*)(smem + aBase + r1 * 128 + (bo1 ^ sw0));
                }
                #pragma unroll
                for (int mc = 0; mc < 4; mc++) {
                    int n = warpCol * 32 + mc * 8 + g;
                    uint32_t sw = (n & 7) << 4;
                    bf[mc][0] = *(const uint32_t*)(smem + bBase + n * 128 + (bo0 ^ sw));
                    bf[mc][1] = *(const uint32_t*)(smem + bBase + n * 128 + (bo1 ^ sw));
                }
                #pragma unroll
                for (int mr = 0; mr < 4; mr++)
                    #pragma unroll
                    for (int mc = 0; mc < 4; mc++)
                        asm volatile(
                            "mma.sync.aligned.m16n8k16.row.col.f32.f16.f16.f32 "
                            "{%0,%1,%2,%3}, {%4,%5,%6,%7}, {%8,%9}, {%0,%1,%2,%3};"
                            : "+f"(acc[mr][mc][0]), "+f"(acc[mr][mc][1]),
                              "+f"(acc[mr][mc][2]), "+f"(acc[mr][mc][3])
                            : "r"(af[mr][0]), "r"(af[mr][1]), "r"(af[mr][2]), "r"(af[mr][3]),
                              "r"(bf[mc][0]), "r"(bf[mc][1]));
            }
        }
    }

    // ---------------- epilogue ----------------
    // acc element mapping (m16n8k16): c0:(g, tig*2) c1:(g, tig*2+1)
    //                                 c2:(g+8, tig*2) c3:(g+8, tig*2+1)
    int rloc[8], cloc[8], labR[8], labC[8];
    float sqR[8], sqC[8];
    #pragma unroll
    for (int mr = 0; mr < 4; mr++)
        #pragma unroll
        for (int sub = 0; sub < 2; sub++) {
            int s = mr * 2 + sub;
            rloc[s] = warpRow * 64 + mr * 16 + g + sub * 8;
            sqR[s] = sSqRow[rloc[s]];  labR[s] = sLabRow[rloc[s]];
        }
    #pragma unroll
    for (int mc = 0; mc < 4; mc++)
        #pragma unroll
        for (int q = 0; q < 2; q++) {
            int s = mc * 2 + q;
            cloc[s] = warpCol * 32 + mc * 8 + tig * 2 + q;
            sqC[s] = sSqCol[cloc[s]];  labC[s] = sLabCol[cloc[s]];
        }

    int rPb[8], rPi[8], rNb[8], rNi[8], cPb[8], cPi[8], cNb[8], cNi[8];
    #pragma unroll
    for (int s = 0; s < 8; s++) {
        rPb[s] = (int)0xFF800000u; rPi[s] = 0x7FFFFFFF;
        rNb[s] = 0x7F800000;       rNi[s] = 0x7FFFFFFF;
        cPb[s] = (int)0xFF800000u; cPi[s] = 0x7FFFFFFF;
        cNb[s] = 0x7F800000;       cNi[s] = 0x7FFFFFFF;
    }

    #pragma unroll
    for (int mr = 0; mr < 4; mr++)
        #pragma unroll
        for (int sub = 0; sub < 2; sub++) {
            const int rs = mr * 2 + sub;
            const int i = rowBase + rloc[rs];
            #pragma unroll
            for (int mc = 0; mc < 4; mc++)
                #pragma unroll
                for (int q = 0; q < 2; q++) {
                    const int cs = mc * 2 + q;
                    const int j = colBase + cloc[cs];
                    float dot = acc[mr][mc][sub * 2 + q];
                    float d2 = fmaxf(fmaf(-2.0f, dot, sqR[rs] + sqC[cs]), 0.0f);
                    const bool same = (labR[rs] == labC[cs]);
                    int bp = (same && (i != j)) ? __float_as_int(d2) : 0;
                    int bn = same ? 0x7F800000 : __float_as_int(d2);
                    if (gtPos(bp, j, rPb[rs], rPi[rs])) { rPb[rs] = bp; rPi[rs] = j; }
                    if (ltNeg(bn, j, rNb[rs], rNi[rs])) { rNb[rs] = bn; rNi[rs] = j; }
                    if (gtPos(bp, i, cPb[cs], cPi[cs])) { cPb[cs] = bp; cPi[cs] = i; }
                    if (ltNeg(bn, i, cNb[cs], cNi[cs])) { cNb[cs] = bn; cNi[cs] = i; }
                }
        }

    // row-side: merge across the 4 lanes sharing each row (width-4 tree)
    #pragma unroll
    for (int s = 0; s < 8; s++) {
        #pragma unroll
        for (int d = 1; d < 4; d <<= 1) {
            int ob = __shfl_down_sync(0xffffffffu, rPb[s], d, 4);
            int oi = __shfl_down_sync(0xffffffffu, rPi[s], d, 4);
            if (gtPos(ob, oi, rPb[s], rPi[s])) { rPb[s] = ob; rPi[s] = oi; }
            ob = __shfl_down_sync(0xffffffffu, rNb[s], d, 4);
            oi = __shfl_down_sync(0xffffffffu, rNi[s], d, 4);
            if (ltNeg(ob, oi, rNb[s], rNi[s])) { rNb[s] = ob; rNi[s] = oi; }
        }
        // col-side: lanes sharing a col are stride-4 apart
        #pragma unroll
        for (int d = 4; d < 32; d <<= 1) {
            int ob = __shfl_down_sync(0xffffffffu, cPb[s], d, 32);
            int oi = __shfl_down_sync(0xffffffffu, cPi[s], d, 32);
            if (gtPos(ob, oi, cPb[s], cPi[s])) { cPb[s] = ob; cPi[s] = oi; }
            ob = __shfl_down_sync(0xffffffffu, cNb[s], d, 32);
            oi = __shfl_down_sync(0xffffffffu, cNi[s], d, 32);
            if (ltNeg(ob, oi, cNb[s], cNi[s])) { cNb[s] = ob; cNi[s] = oi; }
        }
    }

    // finalists -> dist domain, packed u64, smem atomic merge
    if (tig == 0) {
        #pragma unroll
        for (int s = 0; s < 8; s++) {
            float pd = __fsqrt_rn(__int_as_float(rPb[s]));
            float nd = __fsqrt_rn(__int_as_float(rNb[s]));
            u64t kp = ((u64t)__float_as_uint(pd) << 32) | (u64t)(NN - 1 - rPi[s]);
            u64t kn = ((u64t)__float_as_uint(nd) << 32) | (u64t)rNi[s];
            atomicMax(&sRowP[rloc[s]], kp);
            atomicMin(&sRowN[rloc[s]], kn);
        }
    }
    if (g == 0) {
        #pragma unroll
        for (int s = 0; s < 8; s++) {
            float pd = __fsqrt_rn(__int_as_float(cPb[s]));
            float nd = __fsqrt_rn(__int_as_float(cNb[s]));
            u64t kp = ((u64t)__float_as_uint(pd) << 32) | (u64t)(NN - 1 - cPi[s]);
            u64t kn = ((u64t)__float_as_uint(nd) << 32) | (u64t)cNi[s];
            atomicMax(&sColP[cloc[s]], kp);
            atomicMin(&sColN[cloc[s]], kn);
        }
    }
    __syncthreads();
    if (tid < MT) {
        atomicMax(&g_posP[rowBase + tid], sRowP[tid]);
        atomicMin(&g_negP[rowBase + tid], sRowN[tid]);
        if (offdiag) {
            atomicMax(&g_posP[colBase + tid], sColP[tid]);
            atomicMin(&g_negP[colBase + tid], sColN[tid]);
        }
    }
}

// Outputs as FLOAT32 (harness normalizes reference int/bool to float32)
__global__ void final_kernel(float* __restrict__ out) {
    int i = blockIdx.x * blockDim.x + threadIdx.x;
    if (i >= NN) return;
    const int bpi = NN - 1 - (int)(g_posP[i] & 0xffffffffu);
    const int bni = (int)(g_negP[i] & 0xffffffffu);
    const int c = g_cnt[g_lab[i] & (NC - 1)];
    const float keep = (c >= 2 && c < NN) ? 1.0f : 0.0f;
    out[0 * NN + i] = (float)i;
    out[1 * NN + i] = (float)bpi;
    out[2 * NN + i] = (float)bni;
    out[3 * NN + i] = keep;
}

extern "C" void kernel_launch(void* const* d_in, const int* in_sizes, int n_in,
                              void* d_out, int out_size) {
    const float* embeds = (const float*)d_in[0];
    const void*  labels = d_in[1];
    float* out = (float*)d_out;

    cudaFuncSetAttribute(mine_kernel,
                         cudaFuncAttributeMaxDynamicSharedMemorySize, SMEM_TOTAL);

    detect_kernel<<<1, 32>>>((const int*)labels);
    convert_labels_kernel<<<(NN + 255) / 256, 256>>>(labels);
    hist_kernel<<<(NN + 255) / 256, 256>>>();
    normalize_split_kernel<<<NN, DD>>>(embeds);
    mine_kernel<<<NPAIRS, 256, SMEM_TOTAL>>>();
    final_kernel<<<(NN + 255) / 256, 256>>>(out);
}

// round 14
// speedup vs baseline: 2.1829x; 2.1829x over previous
#include <cuda_runtime.h>
#include <math.h>

#define NN 8192
#define DD 128
#define NC 256
#define TILE 128
#define NTILE (NN / TILE)                   // 64
#define NPAIRS (NTILE * (NTILE + 1) / 2)    // 2080
#define NCHUNK (DD / 8)                     // 16 k-chunks of 8

typedef unsigned long long u64t;

// Scratch (device globals — no allocation allowed)
__device__ float g_xn[NN * DD];
__device__ float g_sq[NN];
__device__ int   g_lab[NN];
__device__ int   g_cnt[NC];
__device__ int   g_is64;
__device__ u64t  g_posP[NN];   // packed (bits(dist)<<32)|(NN-1-j), merged via atomicMax
__device__ u64t  g_negP[NN];   // packed (bits(dist)<<32)|j,        merged via atomicMin

#define F_INF  __int_as_float(0x7f800000)

// Packed fp32x2 helpers (each lane is IEEE fp32 fma.rn — bitwise identical to
// scalar fmaf). FFMA2 is throughput-neutral on sm_103a but halves instr count,
// freeing issue slots for LDS/epilogue.
__device__ __forceinline__ u64t pack2_dup(float v) {
    u64t r; asm("mov.b64 %0, {%1, %1};" : "=l"(r) : "f"(v)); return r;
}
__device__ __forceinline__ void ffma2(u64t& d, u64t a, u64t b) {
    asm("fma.rn.f32x2 %0, %1, %2, %0;" : "+l"(d) : "l"(a), "l"(b));
}
__device__ __forceinline__ void unpack2(float& lo, float& hi, u64t v) {
    asm("mov.b64 {%0, %1}, %2;" : "=f"(lo), "=f"(hi) : "l"(v));
}

__device__ __forceinline__ u64t packPos(float v, int j) {
    return ((u64t)__float_as_uint(v) << 32) | (u64t)(NN - 1 - j);
}
__device__ __forceinline__ u64t packNeg(float v, int j) {
    return ((u64t)__float_as_uint(v) << 32) | (u64t)j;
}

// One block: detect int64 labels (labels < 256 => high words zero) + zero g_cnt
__global__ void init_kernel(const int* __restrict__ labw) {
    int t = threadIdx.x;
    __shared__ int sAny[256];
    sAny[t] = labw[2 * t + 1];
    __syncthreads();
    if (t == 0) {
        int any = 0;
        for (int i = 0; i < 256; i++) any |= sAny[i];
        g_is64 = (any == 0) ? 1 : 0;
    }
    if (t < NC) g_cnt[t] = 0;
}

// Fused: convert labels + histogram + reset packed stat arrays
__global__ void convert_hist_kernel(const void* __restrict__ labels) {
    int i = blockIdx.x * blockDim.x + threadIdx.x;
    if (i >= NN) return;
    int v;
    if (g_is64) v = (int)((const long long*)labels)[i];
    else        v = ((const int*)labels)[i];
    g_lab[i] = v;
    g_posP[i] = 0ull;            // any entry (dist>=0) wins or ties
    g_negP[i] = ~0ull;           // any entry smaller
    atomicAdd(&g_cnt[v & (NC - 1)], 1);
}

// 8 rows per 1024-thread block; per-row numerics BIT-IDENTICAL to the proven
// 1-row/128-thread version (same 4-warp shfl tree, same ws sum order).
__global__ void normalize_kernel(const float* __restrict__ x) {
    const int sub = threadIdx.x >> 7;     // row slot 0..7 in block
    const int t   = threadIdx.x & 127;    // 0..127 within row
    const int row = blockIdx.x * 8 + sub;
    float v = x[row * DD + t];
    float s = v * v;
    #pragma unroll
    for (int o = 16; o > 0; o >>= 1) s += __shfl_xor_sync(0xffffffffu, s, o);
    __shared__ float ws[8][4];
    __shared__ float ws2[8][4];
    int warp = t >> 5, lane = t & 31;
    if (lane == 0) ws[sub][warp] = s;
    __syncthreads();
    float tot = ws[sub][0] + ws[sub][1] + ws[sub][2] + ws[sub][3];
    float nrm = __fsqrt_rn(tot);          // IEEE, matches jnp
    float xn  = __fdiv_rn(v, nrm);        // IEEE divide, matches x / norm
    g_xn[row * DD + t] = xn;
    float s2 = xn * xn;
    #pragma unroll
    for (int o = 16; o > 0; o >>= 1) s2 += __shfl_xor_sync(0xffffffffu, s2, o);
    if (lane == 0) ws2[sub][warp] = s2;
    __syncthreads();
    if (t == 0) g_sq[row] = ws2[sub][0] + ws2[sub][1] + ws2[sub][2] + ws2[sub][3];
}

// Triangular miner (PROVEN 242.4us version, unchanged): one CTA per 128x128
// tile (I,J), J >= I. d(i,j)=d(j,i) bitwise (same k-order FMA chain), so
// off-diagonal tiles serve BOTH row anchors and col anchors. Merging via
// packed u64 atomics encodes the exact argmax/argmin-first-index tie rule.
__global__ void __launch_bounds__(256, 2)
mine_kernel() {
    // decode triangular pair index
    int t = blockIdx.x, I = 0;
    while (t >= NTILE - I) { t -= NTILE - I; I++; }
    const int J = I + t;
    const int rowBase = I * TILE;
    const int colBase = J * TILE;
    const bool offdiag = (I != J);

    __shared__ float sA[2][8][TILE];
    __shared__ float sB[2][8][TILE];
    __shared__ float sSqRow[TILE];
    __shared__ float sSqCol[TILE];
    __shared__ int   sLabRow[TILE];
    __shared__ int   sLabCol[TILE];
    __shared__ u64t  sPc[TILE];
    __shared__ u64t  sNc[TILE];

    const int tid = threadIdx.x;
    const int tx = tid & 15;      // column group 0..15
    const int ty = tid >> 4;      // row group 0..15

    if (tid < TILE) {
        sLabRow[tid] = g_lab[rowBase + tid];
        sSqRow[tid]  = g_sq[rowBase + tid];
        sLabCol[tid] = g_lab[colBase + tid];
        sSqCol[tid]  = g_sq[colBase + tid];
        sPc[tid] = 0ull;
        sNc[tid] = ~0ull;
    }

    const int loadRow = tid >> 1;          // 0..127
    const int loadK4  = (tid & 1) * 4;     // 0 or 4
    const float* gA = &g_xn[(rowBase + loadRow) * DD + loadK4];
    const float* gB = &g_xn[(colBase + loadRow) * DD + loadK4];

    // preload chunk 0 into buffer 0
    float4 av = *(const float4*)&gA[0];
    float4 bv = *(const float4*)&gB[0];
    sA[0][loadK4 + 0][loadRow] = av.x;
    sA[0][loadK4 + 1][loadRow] = av.y;
    sA[0][loadK4 + 2][loadRow] = av.z;
    sA[0][loadK4 + 3][loadRow] = av.w;
    sB[0][loadK4 + 0][loadRow] = bv.x;
    sB[0][loadK4 + 1][loadRow] = bv.y;
    sB[0][loadK4 + 2][loadRow] = bv.z;
    sB[0][loadK4 + 3][loadRow] = bv.w;
    __syncthreads();

    u64t acc2[8][4];
    #pragma unroll
    for (int i = 0; i < 8; i++)
        #pragma unroll
        for (int p = 0; p < 4; p++) acc2[i][p] = 0ull;

    #pragma unroll 1
    for (int c = 0; c < NCHUNK; ++c) {
        const int buf = c & 1;
        if (c + 1 < NCHUNK) {
            av = *(const float4*)&gA[(c + 1) * 8];
            bv = *(const float4*)&gB[(c + 1) * 8];
        }
        #pragma unroll
        for (int k = 0; k < 8; k++) {
            float4 a0 = *(const float4*)&sA[buf][k][ty * 4];
            float4 a1 = *(const float4*)&sA[buf][k][64 + ty * 4];
            ulonglong2 bq0 = *(const ulonglong2*)&sB[buf][k][tx * 4];
            ulonglong2 bq1 = *(const ulonglong2*)&sB[buf][k][64 + tx * 4];
            u64t bp[4] = {bq0.x, bq0.y, bq1.x, bq1.y};
            u64t a2[8];
            a2[0] = pack2_dup(a0.x); a2[1] = pack2_dup(a0.y);
            a2[2] = pack2_dup(a0.z); a2[3] = pack2_dup(a0.w);
            a2[4] = pack2_dup(a1.x); a2[5] = pack2_dup(a1.y);
            a2[6] = pack2_dup(a1.z); a2[7] = pack2_dup(a1.w);
            #pragma unroll
            for (int i = 0; i < 8; i++)
                #pragma unroll
                for (int p = 0; p < 4; p++)
                    ffma2(acc2[i][p], a2[i], bp[p]);
        }
        if (c + 1 < NCHUNK) {
            const int nb = (c + 1) & 1;
            sA[nb][loadK4 + 0][loadRow] = av.x;
            sA[nb][loadK4 + 1][loadRow] = av.y;
            sA[nb][loadK4 + 2][loadRow] = av.z;
            sA[nb][loadK4 + 3][loadRow] = av.w;
            sB[nb][loadK4 + 0][loadRow] = bv.x;
            sB[nb][loadK4 + 1][loadRow] = bv.y;
            sB[nb][loadK4 + 2][loadRow] = bv.z;
            sB[nb][loadK4 + 3][loadRow] = bv.w;
            __syncthreads();
        }
    }

    // Col-anchor packed stats (candidate index = row i)
    u64t colP[8], colN[8];
    #pragma unroll
    for (int s = 0; s < 8; s++) { colP[s] = 0ull; colN[s] = ~0ull; }

    // Epilogue: dist = sqrt(max(sq_i + sq_j - 2*dot, 0)); IEEE sqrt to
    // reproduce reference values exactly. Row-side: candidates = tile cols;
    // col-side (offdiag only): candidates = tile rows, same dist values.
    #pragma unroll
    for (int ii = 0; ii < 8; ii++) {
        const int  ri  = (ii < 4) ? (ty * 4 + ii) : (64 + ty * 4 + ii - 4);
        const int  i   = rowBase + ri;
        const int  lr  = sLabRow[ri];
        const float sr = sSqRow[ri];
        u64t rp = 0ull, rn = ~0ull;
        #pragma unroll
        for (int p = 0; p < 4; p++) {
            float d_lo, d_hi;
            unpack2(d_lo, d_hi, acc2[ii][p]);
            const float dotv[2] = {d_lo, d_hi};
            #pragma unroll
            for (int q = 0; q < 2; q++) {
                const int s  = p * 2 + q;
                const int jc = (p < 2) ? (tx * 4 + p * 2 + q)
                                       : (64 + tx * 4 + (p - 2) * 2 + q);
                const int j  = colBase + jc;
                float d2 = fmaxf(sr + sSqCol[jc] - 2.0f * dotv[q], 0.0f);
                float dist = __fsqrt_rn(d2);
                const bool same = (lr == sLabCol[jc]);
                const bool diag = (i == j);
                // row anchor i, candidate j
                const float pv = (same && !diag) ? dist : 0.0f;
                const float nv = same ? F_INF : dist;
                u64t pp = packPos(pv, j);
                if (pp > rp) rp = pp;
                u64t np = packNeg(nv, j);
                if (np < rn) rn = np;
                // col anchor j, candidate i (offdiag: i != j always)
                u64t cp = packPos(pv, i);   // same mask values by symmetry
                if (cp > colP[s]) colP[s] = cp;
                u64t cn = packNeg(nv, i);
                if (cn < colN[s]) colN[s] = cn;
            }
        }
        // reduce row stats over the 16 tx threads (one 16-lane half-warp)
        #pragma unroll
        for (int off = 8; off > 0; off >>= 1) {
            u64t orp = __shfl_down_sync(0xffffffffu, rp, off, 16);
            u64t orn = __shfl_down_sync(0xffffffffu, rn, off, 16);
            if (orp > rp) rp = orp;
            if (orn < rn) rn = orn;
        }
        if (tx == 0) {
            atomicMax(&g_posP[i], rp);
            atomicMin(&g_negP[i], rn);
        }
    }

    if (offdiag) {
        // merge col stats into smem, then one global RED per column
        #pragma unroll
        for (int p = 0; p < 4; p++) {
            #pragma unroll
            for (int q = 0; q < 2; q++) {
                const int s  = p * 2 + q;
                const int jc = (p < 2) ? (tx * 4 + p * 2 + q)
                                       : (64 + tx * 4 + (p - 2) * 2 + q);
                atomicMax(&sPc[jc], colP[s]);
                atomicMin(&sNc[jc], colN[s]);
            }
        }
        __syncthreads();
        if (tid < TILE) {
            atomicMax(&g_posP[colBase + tid], sPc[tid]);
            atomicMin(&g_negP[colBase + tid], sNc[tid]);
        }
    }
}

// Outputs written as FLOAT32 (harness normalizes reference int/bool outputs
// to float32; indices < 8192 exactly representable).
__global__ void final_kernel(float* __restrict__ out) {
    int i = blockIdx.x * blockDim.x + threadIdx.x;
    if (i >= NN) return;
    const int bpi = NN - 1 - (int)(g_posP[i] & 0xffffffffu);
    const int bni = (int)(g_negP[i] & 0xffffffffu);
    const int c = g_cnt[g_lab[i] & (NC - 1)];
    const float keep = (c >= 2 && c < NN) ? 1.0f : 0.0f;
    out[0 * NN + i] = (float)i;    // anchor_inds
    out[1 * NN + i] = (float)bpi;  // hardest_pos_inds
    out[2 * NN + i] = (float)bni;  // hardest_neg_inds
    out[3 * NN + i] = keep;        // keep
}

extern "C" void kernel_launch(void* const* d_in, const int* in_sizes, int n_in,
                              void* d_out, int out_size) {
    const float* embeds = (const float*)d_in[0];
    const void*  labels = d_in[1];
    float* out = (float*)d_out;

    init_kernel<<<1, 256>>>((const int*)labels);
    convert_hist_kernel<<<(NN + 255) / 256, 256>>>(labels);
    normalize_kernel<<<NN / 8, 1024>>>(embeds);
    mine_kernel<<<NPAIRS, 256>>>();
    final_kernel<<<(NN + 255) / 256, 256>>>(out);
}